// round 17
// baseline (speedup 1.0000x reference)
#include <cuda_runtime.h>
#include <cstdint>

#define T_LEN   2097152
#define KK      8
#define DD      4
#define CHUNK   56
#define NCHUNK  37888           // CHUNK*NCHUNK = 2121728 >= T_LEN-1
#define NGRP    18944           // 8-lane groups; chain A: g, chain B: g+NGRP
#define NBLK    592             // NGRP/32 -> exactly 4 blocks/SM on 148 SMs
#define WARM    24
#define NSAMP   1024
#define NSBLK   32              // sample blocks
#define SAMP_ACC 32
#define SAMP_WARM 16

#define LOG_2PI_F 1.8378770664093453f

// ---------------- device scratch ----------------
__device__ float  g_samp[NSBLK];   // per-sample-block partial sums (overwritten each launch)
__device__ double g_sum;           // accumulated scale sum (atomic; reset by hmm_sample)
__device__ float  g_dfin[KK];      // final relative state
__device__ unsigned g_done;        // finished-block counter (reset by hmm_sample)

// ---------------- inline constant computation (per thread, state j) ----------------
__device__ __forceinline__ void load_consts(const float* __restrict__ tr,
                                            const float* __restrict__ means,
                                            const float* __restrict__ log_std,
                                            int j, float ltrc[8], float& ca,
                                            float cb[4], float cg[4])
{
    #pragma unroll
    for (int i = 0; i < 8; i++) {
        float m = -1e30f;
        #pragma unroll
        for (int q = 0; q < 8; q++) m = fmaxf(m, tr[i*8+q]);
        float s = 0.f;
        #pragma unroll
        for (int q = 0; q < 8; q++) s += expf(tr[i*8+q] - m);
        ltrc[i] = (tr[i*8+j] - m) - logf(s);
    }
    ca = 0.f;
    #pragma unroll
    for (int d = 0; d < 4; d++) {
        float lsd = log_std[j*4+d];
        float iv  = expf(-2.0f * lsd);
        float mu  = means[j*4+d];
        ca += -0.5f*LOG_2PI_F - lsd - 0.5f*mu*mu*iv;
        cb[d] = mu*iv;
        cg[d] = -0.5f*iv;
    }
}

// grid constants for binade exponent e (|alpha| in [2^e, 2^{e+1}))
__device__ __forceinline__ void setgrid(int e, float& C, float& thresh,
                                        float E[8], const float ltrc[8])
{
    thresh = __int_as_float((e + 128) << 23);                     // 2^{e+1}
    C = (e >= 8) ? 1.5f * __int_as_float((e + 127) << 23) : 0.f;  // 1.5*2^e
    #pragma unroll
    for (int i = 0; i < 8; i++) {
        float q = __fadd_rn(__fadd_rn(ltrc[i], C), -C);           // rnd_u(ltr) (RNE)
        E[i] = expf(q);
    }
}

// ---------------- sampling pass: estimate mean per-step scale m_bar ----------------
__global__ __launch_bounds__(256) void hmm_sample(const float* __restrict__ x,
                                                  const float* __restrict__ tr,
                                                  const float* __restrict__ means,
                                                  const float* __restrict__ log_std)
{
    const int lane  = threadIdx.x & 31;
    const int j     = lane & 7;
    const int base  = lane & 24;
    const unsigned gm = 0xFFu << base;
    const int warp  = threadIdx.x >> 5;
    const int g     = (((blockIdx.x * blockDim.x + threadIdx.x) >> 5) << 2) + (lane >> 3);

    __shared__ float ssum[32];

    if (blockIdx.x == 0 && threadIdx.x == 0) {   // reset accumulators for this launch
        g_sum  = 0.0;
        g_done = 0u;
    }

    float ltrc[8], cca, cb[4], cg[4];
    load_consts(tr, means, log_std, j, ltrc, cca, cb, cg);

    float E[8];
    #pragma unroll
    for (int i = 0; i < 8; i++) E[i] = expf(ltrc[i]);

    const float4* xp = reinterpret_cast<const float4*>(x);
    const int t0 = SAMP_WARM + 1 + g * 2047;     // windows spread over the sequence
    float d = 0.f, S = 0.f;

    #pragma unroll 1
    for (int k = 0; k < SAMP_WARM + SAMP_ACC; k++) {
        int tt = t0 - SAMP_WARM + k;
        float4 xv = xp[tt];
        float p = cca;
        p = fmaf(xv.x, fmaf(cg[0], xv.x, cb[0]), p);
        p = fmaf(xv.y, fmaf(cg[1], xv.y, cb[1]), p);
        p = fmaf(xv.z, fmaf(cg[2], xv.z, cb[2]), p);
        p = fmaf(xv.w, fmaf(cg[3], xv.w, cb[3]), p);
        float w = __expf(d);
        float wi, acc;
        wi = __shfl_sync(gm, w, base + 0); acc = wi * E[0];
        wi = __shfl_sync(gm, w, base + 1); acc = fmaf(wi, E[1], acc);
        wi = __shfl_sync(gm, w, base + 2); acc = fmaf(wi, E[2], acc);
        wi = __shfl_sync(gm, w, base + 3); acc = fmaf(wi, E[3], acc);
        wi = __shfl_sync(gm, w, base + 4); acc = fmaf(wi, E[4], acc);
        wi = __shfl_sync(gm, w, base + 5); acc = fmaf(wi, E[5], acc);
        wi = __shfl_sync(gm, w, base + 6); acc = fmaf(wi, E[6], acc);
        wi = __shfl_sync(gm, w, base + 7); acc = fmaf(wi, E[7], acc);
        float av = __logf(acc) + p;
        float av0 = __shfl_sync(gm, av, base);
        d = av - av0;
        if (k >= SAMP_WARM) S += av0;
    }
    if (j == 0) ssum[warp * 4 + (lane >> 3)] = S;
    __syncthreads();
    if (threadIdx.x == 0) {
        float t = 0.f;
        #pragma unroll
        for (int q = 0; q < 32; q++) t += ssum[q];
        g_samp[blockIdx.x] = t;
    }
}

// ---------------- main quantized pass, 2 chains per 8-lane group ----------------
__global__ __launch_bounds__(256, 4) void hmm_quant(const float* __restrict__ x,
                                                    const float* __restrict__ tr,
                                                    const float* __restrict__ pi,
                                                    const float* __restrict__ means,
                                                    const float* __restrict__ log_std,
                                                    float* __restrict__ out)
{
    const int lane  = threadIdx.x & 31;
    const int j     = lane & 7;
    const int base  = lane & 24;
    const unsigned gm = 0xFFu << base;
    const int warp  = threadIdx.x >> 5;
    const int g     = (((blockIdx.x * blockDim.x + threadIdx.x) >> 5) << 2) + (lane >> 3);
    const int cA = g, cB = g + NGRP;

    __shared__ double sred[32];

    float ltrc[8], cca, cb[4], cg[4];
    load_consts(tr, means, log_std, j, ltrc, cca, cb, cg);

    float msum = 0.f;
    #pragma unroll
    for (int q = 0; q < NSBLK; q++) msum += g_samp[q];
    const float mbar = msum * (1.0f / (float)(NSAMP * SAMP_ACC));

    const int tbA = 1 + cA * CHUNK;
    const int tbB = 1 + cB * CHUNK;
    const float4* xp = reinterpret_cast<const float4*>(x);

    float dA, dB, SA = 0.f, SB = 0.f, curA, curB;
    const bool wA = (cA != 0);

    if (!wA) {
        // exact alpha0 = log_pi + log_em[0]
        float pm = -1e30f;
        #pragma unroll
        for (int q = 0; q < 8; q++) pm = fmaxf(pm, pi[q]);
        float ps = 0.f;
        #pragma unroll
        for (int q = 0; q < 8; q++) ps += expf(pi[q] - pm);
        float lpij = (pi[j] - pm) - logf(ps);

        float4 x0 = xp[0];
        float p = cca;
        p = fmaf(x0.x, fmaf(cg[0], x0.x, cb[0]), p);
        p = fmaf(x0.y, fmaf(cg[1], x0.y, cb[1]), p);
        p = fmaf(x0.z, fmaf(cg[2], x0.z, cb[2]), p);
        p = fmaf(x0.w, fmaf(cg[3], x0.w, cb[3]), p);
        float a0 = lpij + p;
        float a00 = __shfl_sync(gm, a0, base);
        dA = a0 - a00;
        SA = a00;
        curA = a00;
    } else {
        dA = 0.f;
        curA = mbar * (float)(tbA - WARM);
    }
    dB = 0.f;
    curB = mbar * (float)(tbB - WARM);

    float CA, CB, thA, thB, EA[8], EB[8];
    {
        int eA = (__float_as_int(fmaxf(fabsf(curA), 1.0f)) >> 23) - 127;
        int eB = (__float_as_int(fmaxf(fabsf(curB), 1.0f)) >> 23) - 127;
        setgrid(eA, CA, thA, EA, ltrc);
        setgrid(eB, CB, thB, EB, ltrc);
    }

#define HMM_STEP(d_, S_, cur_, C_, th_, E_, tt, COMMIT, ACCUM)                \
    {                                                                         \
        float4 xv = xp[tt];                                                   \
        float p = cca;                                                        \
        p = fmaf(xv.x, fmaf(cg[0], xv.x, cb[0]), p);                          \
        p = fmaf(xv.y, fmaf(cg[1], xv.y, cb[1]), p);                          \
        p = fmaf(xv.z, fmaf(cg[2], xv.z, cb[2]), p);                          \
        p = fmaf(xv.w, fmaf(cg[3], xv.w, cb[3]), p);                          \
        float em = __fadd_rn(__fadd_rn(p, C_), -C_);                          \
        float w = __expf(d_);                                                 \
        float wi, acc;                                                        \
        wi = __shfl_sync(gm, w, base + 0); acc = wi * E_[0];                  \
        wi = __shfl_sync(gm, w, base + 1); acc = fmaf(wi, E_[1], acc);        \
        wi = __shfl_sync(gm, w, base + 2); acc = fmaf(wi, E_[2], acc);        \
        wi = __shfl_sync(gm, w, base + 3); acc = fmaf(wi, E_[3], acc);        \
        wi = __shfl_sync(gm, w, base + 4); acc = fmaf(wi, E_[4], acc);        \
        wi = __shfl_sync(gm, w, base + 5); acc = fmaf(wi, E_[5], acc);        \
        wi = __shfl_sync(gm, w, base + 6); acc = fmaf(wi, E_[6], acc);        \
        wi = __shfl_sync(gm, w, base + 7); acc = fmaf(wi, E_[7], acc);        \
        float L = __logf(acc);                                                \
        float lse = __fadd_rn(__fadd_rn(L, C_), -C_);                         \
        float av = lse + em;                                                  \
        float av0 = __shfl_sync(gm, av, base);                                \
        if (COMMIT) {                                                         \
            d_ = av - av0;                                                    \
            if (ACCUM) S_ += av0;                                             \
            cur_ += av0;                                                      \
            if (fabsf(cur_) >= th_) {                                         \
                int e2 = (__float_as_int(fabsf(cur_)) >> 23) - 127;           \
                setgrid(e2, C_, th_, E_, ltrc);                               \
            }                                                                 \
        }                                                                     \
    }

    // warm-up (chunk 0's chain A executes but never commits)
    #pragma unroll 1
    for (int k = 0; k < WARM; k++) {
        int tA = wA ? (tbA - WARM + k) : 0;
        int tB = min(tbB - WARM + k, T_LEN - 1);
        HMM_STEP(dA, SA, curA, CA, thA, EA, tA, wA, false)
        HMM_STEP(dB, SB, curB, CB, thB, EB, tB, true, false)
    }
    // main accumulating region
    #pragma unroll 1
    for (int k = 0; k < CHUNK; k++) {
        int tA = tbA + k;                       // always < T_LEN for cA < NGRP
        int tB = tbB + k;
        bool vB = (tB < T_LEN);
        int tBc = vB ? tB : (T_LEN - 1);
        HMM_STEP(dA, SA, curA, CA, thA, EA, tA, true, true)
        HMM_STEP(dB, SB, curB, CB, thB, EB, tBc, vB, vB)
    }
#undef HMM_STEP

    // final relative state lives in the chunk containing t = T_LEN-1
    const int lastc = (T_LEN - 2) / CHUNK;      // chunk index of final step
    if (cB == lastc) g_dfin[j] = dB;
    if (cA == lastc) g_dfin[j] = dA;            // (only one of these matches)

    // ---- in-block reduction of chunk sums, one atomic per block ----
    if (j == 0) sred[warp * 4 + (lane >> 3)] = (double)SA + (double)SB;
    __syncthreads();
    if (threadIdx.x == 0) {
        double t = 0.0;
        #pragma unroll
        for (int q = 0; q < 32; q++) t += sred[q];
        atomicAdd(&g_sum, t);
        __threadfence();
        unsigned ticket = atomicAdd(&g_done, 1u);
        if (ticket == NBLK - 1) {
            // all blocks' g_sum/g_dfin contributions are visible
            __threadfence();
            float m = -1e30f;
            #pragma unroll
            for (int i = 0; i < 8; i++) m = fmaxf(m, g_dfin[i]);
            float acc = 0.f;
            #pragma unroll
            for (int i = 0; i < 8; i++) acc += __expf(g_dfin[i] - m);
            double total = g_sum + (double)m + (double)__logf(acc);
            out[0] = (float)total;
        }
    }
}

// ---------------- launch ----------------
extern "C" void kernel_launch(void* const* d_in, const int* in_sizes, int n_in,
                              void* d_out, int out_size)
{
    const float* x_seq   = (const float*)d_in[0];
    const float* untrans = (const float*)d_in[1];
    const float* unpi    = (const float*)d_in[2];
    const float* means   = (const float*)d_in[3];
    const float* log_std = (const float*)d_in[4];
    float* out = (float*)d_out;

    hmm_sample<<<NSBLK, 256>>>(x_seq, untrans, means, log_std);
    hmm_quant<<<NBLK, 256>>>(x_seq, untrans, unpi, means, log_std, out);
}